// round 11
// baseline (speedup 1.0000x reference)
#include <cuda_runtime.h>
#include <cstdint>

#define NB 128   // batch
#define NC 16    // c rows
#define NF 128   // f cols
#define ND 512   // feature dim
#define NEG_INF __int_as_float(0xff800000)

// Scratch (no cudaMalloc allowed)
__device__ float g_xnT[NB * ND * NC];     // 4 MB  : xn transposed [m][d][c]
__device__ float g_fT [NB * ND * NF];     // 32 MB : f transposed  [n][d][f]
__device__ float g_fnorm[NB * NF];        // 64 KB

// ---------------------------------------------------------------------------
// Kernel 1: normalize c_feats (store d-major transposed) + f row norms
// ---------------------------------------------------------------------------
__global__ void __launch_bounds__(128) prep_kernel(
    const float* __restrict__ c_feats, const float* __restrict__ f_feats)
{
    const int b   = blockIdx.x;
    const int tid = threadIdx.x;
    const bool is_c = (b < NB * NC);
    const float* row = is_c ? (c_feats + (size_t)b * ND)
                            : (f_feats + (size_t)(b - NB * NC) * ND);
    float4 x = ((const float4*)row)[tid];   // 128 threads * 4 = 512
    float ss = x.x * x.x + x.y * x.y + x.z * x.z + x.w * x.w;
    #pragma unroll
    for (int o = 16; o; o >>= 1) ss += __shfl_xor_sync(0xffffffffu, ss, o);
    __shared__ float wr[4];
    if ((tid & 31) == 0) wr[tid >> 5] = ss;
    __syncthreads();
    float nrm = sqrtf(wr[0] + wr[1] + wr[2] + wr[3]);

    if (is_c) {
        int m = b >> 4, c = b & 15;
        float* dst = g_xnT + (size_t)m * (ND * NC) + c;
        int d0 = tid * 4;
        dst[(size_t)(d0 + 0) * NC] = x.x / nrm;
        dst[(size_t)(d0 + 1) * NC] = x.y / nrm;
        dst[(size_t)(d0 + 2) * NC] = x.z / nrm;
        dst[(size_t)(d0 + 3) * NC] = x.w / nrm;
    } else {
        if (tid == 0) g_fnorm[b - NB * NC] = nrm;
    }
}

// ---------------------------------------------------------------------------
// Kernel 1b: transpose f_feats [n][f][d] -> g_fT [n][d][f]
// ---------------------------------------------------------------------------
__global__ void __launch_bounds__(256) transpose_f_kernel(
    const float* __restrict__ f_feats)
{
    __shared__ float t[32][33];
    const int ft = blockIdx.x, dt = blockIdx.y, n = blockIdx.z;
    const int x = threadIdx.x, y = threadIdx.y;

    const float* src = f_feats + ((size_t)n * NF + ft * 32) * ND + dt * 32;
    #pragma unroll
    for (int r = 0; r < 32; r += 8)
        t[y + r][x] = src[(size_t)(y + r) * ND + x];
    __syncthreads();
    float* dst = g_fT + (size_t)n * (ND * NF) + (size_t)(dt * 32) * NF + ft * 32;
    #pragma unroll
    for (int r = 0; r < 32; r += 8)
        dst[(size_t)(y + r) * NF + x] = t[x][y + r];
}

// ---------------------------------------------------------------------------
// Kernel 2: per-pair register-tiled GEMM (4c x 4f per thread) + DTW.
// Packed operand = f-pair (free from LDG.128); x duplicated at staging time
// so the inner loop has ZERO pack movs: per k = 1 LDG + 2 LDS + 8 FFMA2.
//
// SMEM union (floats), 6432 total (25.7 KB):
//   GEMM phase : xs  [0, 2048)       x chunks duplicated, 2 x [32 k][32]
//   DP phase   : Sbuf[0, 2176)       S [128 f][17]
//                Dm  [2176, 4369)    DP table [17][129]
//                wrs [4376,4380) wrm [4380,4384)
//                mask[4384, 6432)    [16][128]
// ---------------------------------------------------------------------------
#define OFF_DM   2176
#define OFF_WRS  4376
#define OFF_WRM  4380
#define OFF_MASK 4384
#define SMEM_FLOATS 6432

__device__ __forceinline__ void fma2(unsigned long long& d,
                                     unsigned long long a,
                                     unsigned long long b) {
    asm("fma.rn.f32x2 %0, %1, %2, %0;" : "+l"(d) : "l"(a), "l"(b));
}

__global__ void __launch_bounds__(128, 8) dtw_kernel(float* __restrict__ out)
{
    __shared__ float smem[SMEM_FLOATS];
    float* xs   = smem;            // [2][1024] duplicated x
    float* Sbuf = smem;
    float* Dm   = smem + OFF_DM;
    float* wrs  = smem + OFF_WRS;
    float* wrm  = smem + OFF_WRM;
    float* mask = smem + OFF_MASK;

    const int pair = blockIdx.x;
    const int m = pair & 127;      // m fastest -> concurrent CTAs share f[n]
    const int n = pair >> 7;
    const int tid  = threadIdx.x;
    const int lane = tid & 31;
    const int wid  = tid >> 5;
    const int cg   = tid & 3;      // c block: rows 4*cg .. 4*cg+3
    const int fg   = tid >> 2;     // f block: cols 4*fg .. 4*fg+3

    // acc[r][p]: packed pair (S[4cg+r][4fg+2p], S[4cg+r][4fg+2p+1])
    unsigned long long acc[4][2];
    #pragma unroll
    for (int r = 0; r < 4; r++)
        #pragma unroll
        for (int p = 0; p < 2; p++) acc[r][p] = 0ull;

    const float4* xg4 = (const float4*)(g_xnT + (size_t)m * (ND * NC));
    const float*  fT  = g_fT + (size_t)n * (ND * NF);

    // staging indices: thread tid holds x[d][c0..c0+3], d=tid>>2, c0=(tid&3)*4
    const int st_d  = tid >> 2;
    const int st_c0 = (tid & 3) * 4;

    // prime x buffer 0 (duplicate each value: x0,x0,x1,x1,...)
    {
        float4 v = xg4[tid];
        float* dst = xs + st_d * 32 + st_c0 * 2;
        *(float4*)(dst)     = make_float4(v.x, v.x, v.y, v.y);
        *(float4*)(dst + 4) = make_float4(v.z, v.z, v.w, v.w);
    }
    __syncthreads();

    #pragma unroll 1
    for (int chunk = 0; chunk < 16; chunk++) {   // 16 chunks x 32 k
        const float* cur = xs + (chunk & 1) * 1024;
        if (chunk < 15) {
            float4 v = xg4[(chunk + 1) * 128 + tid];
            float* dst = xs + ((chunk + 1) & 1) * 1024 + st_d * 32 + st_c0 * 2;
            *(float4*)(dst)     = make_float4(v.x, v.x, v.y, v.y);
            *(float4*)(dst + 4) = make_float4(v.z, v.z, v.w, v.w);
        }

        const float* fk = fT + (size_t)chunk * 32 * NF + fg * 4;
        #pragma unroll 8
        for (int k = 0; k < 32; k++) {
            // packed f-pairs, straight from gmem (1 L1 line per warp)
            ulonglong2 fp = *(const ulonglong2*)(fk + (size_t)k * NF);
            // duplicated x pairs (broadcast LDS.128, conflict-free)
            const float* xr = cur + k * 32 + cg * 8;
            ulonglong2 xa = *(const ulonglong2*)(xr);      // (x0,x0),(x1,x1)
            ulonglong2 xb = *(const ulonglong2*)(xr + 4);  // (x2,x2),(x3,x3)
            fma2(acc[0][0], xa.x, fp.x); fma2(acc[0][1], xa.x, fp.y);
            fma2(acc[1][0], xa.y, fp.x); fma2(acc[1][1], xa.y, fp.y);
            fma2(acc[2][0], xb.x, fp.x); fma2(acc[2][1], xb.x, fp.y);
            fma2(acc[3][0], xb.y, fp.x); fma2(acc[3][1], xb.y, fp.y);
        }
        __syncthreads();   // next buffer ready + cur free for overwrite
    }

    // ---- spill S to SMEM: Sbuf[f][c], stride 17 ----
    #pragma unroll
    for (int r = 0; r < 4; r++)
        #pragma unroll
        for (int p = 0; p < 2; p++) {
            unsigned long long v = acc[r][p];
            float s0 = __uint_as_float((unsigned)(v & 0xffffffffu));
            float s1 = __uint_as_float((unsigned)(v >> 32));
            int f = fg * 4 + 2 * p, c = cg * 4 + r;
            Sbuf[f * 17 + c]       = s0;
            Sbuf[(f + 1) * 17 + c] = s1;
        }

    const float fnrm = g_fnorm[n * NF + tid];

    // ---- init DP row 0 and zero the mask ----
    Dm[tid + 1] = NEG_INF;
    if (tid == 0) Dm[0] = 0.0f;
    {
        float4 z = make_float4(0.f, 0.f, 0.f, 0.f);
        float4* m4 = (float4*)mask;
        #pragma unroll
        for (int w = 0; w < 4; w++) m4[tid + w * 128] = z;
    }
    __syncthreads();

    // ---- DP rows: D[i,j] = Ccum[j] + cummax_k<=j(A[k] - Ccum[k-1]) ----
    for (int i = 1; i <= NC; i++) {
        const int c = i - 1;
        float s = Sbuf[tid * 17 + c];
        if (tid <= c) s = s / fnrm;   // tri region uses normalized similarity

        const float* Pv = Dm + (size_t)(i - 1) * 129;
        float A = fmaxf(Pv[tid], Pv[tid + 1]);   // max(diag, up)

        // inclusive block cumsum of s
        float cs = s;
        #pragma unroll
        for (int o = 1; o < 32; o <<= 1) {
            float t = __shfl_up_sync(0xffffffffu, cs, o);
            if (lane >= o) cs += t;
        }
        if (lane == 31) wrs[wid] = cs;
        __syncthreads();
        float pre = 0.0f;
        if (wid > 0) pre += wrs[0];
        if (wid > 1) pre += wrs[1];
        if (wid > 2) pre += wrs[2];
        float Ccum = pre + cs;
        // Cm1 = Ccum of thread tid-1, reconstructed bit-exactly:
        float csp = __shfl_up_sync(0xffffffffu, cs, 1);
        float Cm1 = (lane == 0) ? pre : (pre + csp);   // tid==0 -> pre==0
        float T = A - Cm1;

        // inclusive block cummax of T (exact)
        float mx = T;
        #pragma unroll
        for (int o = 1; o < 32; o <<= 1) {
            float t = __shfl_up_sync(0xffffffffu, mx, o);
            if (lane >= o) mx = fmaxf(mx, t);
        }
        if (lane == 31) wrm[wid] = mx;
        __syncthreads();
        if (wid > 0) mx = fmaxf(mx, wrm[0]);
        if (wid > 1) mx = fmaxf(mx, wrm[1]);
        if (wid > 2) mx = fmaxf(mx, wrm[2]);

        Dm[i * 129 + tid + 1] = Ccum + mx;
        if (tid == 0) Dm[i * 129] = NEG_INF;
        __syncthreads();
    }

    // ---- backtrack (argmax first-max: up > left > diag), serial thread ----
    if (tid == 0) {
        int i = NC, j = NF;
        #pragma unroll 1
        for (int step = 0; step < NC + NF && (i > 0 && j > 0); step++) {
            mask[(i - 1) * NF + (j - 1)] = 1.0f;
            float up = Dm[(i - 1) * 129 + j];
            float lf = Dm[i * 129 + (j - 1)];
            float dg = Dm[(i - 1) * 129 + (j - 1)];
            int mv;
            if (up >= lf && up >= dg) mv = 0;
            else if (lf >= dg)        mv = 1;
            else                      mv = 2;
            if (mv != 1) i--;
            if (mv != 0) j--;
        }
    }
    __syncthreads();

    // ---- store mask [16][128] coalesced ----
    {
        float4*       og  = (float4*)(out + (size_t)(m * NB + n) * (NC * NF));
        const float4* ms4 = (const float4*)mask;
        #pragma unroll
        for (int w = 0; w < 4; w++) og[tid + w * 128] = ms4[tid + w * 128];
    }
}

// ---------------------------------------------------------------------------
extern "C" void kernel_launch(void* const* d_in, const int* in_sizes, int n_in,
                              void* d_out, int out_size)
{
    const float* c_feats = (const float*)d_in[0];
    const float* f_feats = (const float*)d_in[1];
    float* out = (float*)d_out;

    prep_kernel<<<NB * NC + NB * NF, 128>>>(c_feats, f_feats);
    transpose_f_kernel<<<dim3(4, 16, NB), dim3(32, 8)>>>(f_feats);
    dtw_kernel<<<NB * NB, 128>>>(out);
}

// round 12
// speedup vs baseline: 1.0555x; 1.0555x over previous
#include <cuda_runtime.h>
#include <cstdint>

#define NB 128   // batch
#define NC 16    // c rows
#define NF 128   // f cols
#define ND 512   // feature dim
#define NEG_INF __int_as_float(0xff800000)

// Scratch (no cudaMalloc allowed)
__device__ float g_xnT[NB * ND * NC];     // 4 MB  : xn transposed [m][d][c]
__device__ float g_fT [NB * ND * NF];     // 32 MB : f transposed  [n][d][f]
__device__ float g_fnorm[NB * NF];        // 64 KB

// ---------------------------------------------------------------------------
// Kernel 1: normalize c_feats (store d-major transposed) + f row norms
// ---------------------------------------------------------------------------
__global__ void __launch_bounds__(128) prep_kernel(
    const float* __restrict__ c_feats, const float* __restrict__ f_feats)
{
    const int b   = blockIdx.x;
    const int tid = threadIdx.x;
    const bool is_c = (b < NB * NC);
    const float* row = is_c ? (c_feats + (size_t)b * ND)
                            : (f_feats + (size_t)(b - NB * NC) * ND);
    float4 x = ((const float4*)row)[tid];
    float ss = x.x * x.x + x.y * x.y + x.z * x.z + x.w * x.w;
    #pragma unroll
    for (int o = 16; o; o >>= 1) ss += __shfl_xor_sync(0xffffffffu, ss, o);
    __shared__ float wr[4];
    if ((tid & 31) == 0) wr[tid >> 5] = ss;
    __syncthreads();
    float nrm = sqrtf(wr[0] + wr[1] + wr[2] + wr[3]);

    if (is_c) {
        int m = b >> 4, c = b & 15;
        float* dst = g_xnT + (size_t)m * (ND * NC) + c;
        int d0 = tid * 4;
        dst[(size_t)(d0 + 0) * NC] = x.x / nrm;
        dst[(size_t)(d0 + 1) * NC] = x.y / nrm;
        dst[(size_t)(d0 + 2) * NC] = x.z / nrm;
        dst[(size_t)(d0 + 3) * NC] = x.w / nrm;
    } else {
        if (tid == 0) g_fnorm[b - NB * NC] = nrm;
    }
}

// ---------------------------------------------------------------------------
// Kernel 1b: transpose f_feats [n][f][d] -> g_fT [n][d][f]
// ---------------------------------------------------------------------------
__global__ void __launch_bounds__(256) transpose_f_kernel(
    const float* __restrict__ f_feats)
{
    __shared__ float t[32][33];
    const int ft = blockIdx.x, dt = blockIdx.y, n = blockIdx.z;
    const int x = threadIdx.x, y = threadIdx.y;

    const float* src = f_feats + ((size_t)n * NF + ft * 32) * ND + dt * 32;
    #pragma unroll
    for (int r = 0; r < 32; r += 8)
        t[y + r][x] = src[(size_t)(y + r) * ND + x];
    __syncthreads();
    float* dst = g_fT + (size_t)n * (ND * NF) + (size_t)(dt * 32) * NF + ft * 32;
    #pragma unroll
    for (int r = 0; r < 32; r += 8)
        dst[(size_t)(y + r) * NF + x] = t[x][y + r];
}

// ---------------------------------------------------------------------------
// Kernel 2: 2 pairs per CTA (m=2q, 2q+1; same n), 64 threads per pair.
// Per-lane tile 4c x 8f, packed-f accumulators (zero pack movs).
// Per k per lane: 2 LDG.128 (f) + 2 LDS.128 (dup x) + 16 FFMA2.
//
// SMEM union (floats), 6432 total (25.7 KB):
//   GEMM phase : xs [0, 4608)   dup x, [2 grp][2 buf][32 k][36]
//   DP phase   : Sbuf[0,2176) Dm[2176,4369) wrs/wrm[4376..4384)
//                mask[4384, 6432)
// ---------------------------------------------------------------------------
#define XST 36                 // dup-x row stride (16B-aligned, low conflicts)
#define XBUF (32 * XST)        // 1152 floats per buffer
#define OFF_DM   2176
#define OFF_WRS  4376
#define OFF_WRM  4380
#define OFF_MASK 4384
#define SMEM_FLOATS 6432

__device__ __forceinline__ void fma2(unsigned long long& d,
                                     unsigned long long a,
                                     unsigned long long b) {
    asm("fma.rn.f32x2 %0, %1, %2, %0;" : "+l"(d) : "l"(a), "l"(b));
}

__global__ void __launch_bounds__(128, 6) dtw_kernel(float* __restrict__ out)
{
    __shared__ float smem[SMEM_FLOATS];
    float* xs   = smem;            // GEMM phase
    float* Sbuf = smem;
    float* Dm   = smem + OFF_DM;
    float* wrs  = smem + OFF_WRS;
    float* wrm  = smem + OFF_WRM;
    float* mask = smem + OFF_MASK;

    const int bid = blockIdx.x;
    const int mbase = (bid & 63) << 1;
    const int n     = bid >> 6;            // consecutive CTAs share n
    const int tid  = threadIdx.x;
    const int lane = tid & 31;
    const int wid  = tid >> 5;
    const int g    = tid >> 6;             // pair group (0/1)
    const int t64  = tid & 63;
    const int fg16 = t64 & 15;             // f block: 8 f at fg16*8
    const int cg   = t64 >> 4;             // c block: 4 c at cg*4
    const int m    = mbase + g;

    // acc[r][p]: packed pair (S[cg*4+r][fg16*8+2p], S[..][..+1])
    unsigned long long acc[4][4];
    #pragma unroll
    for (int r = 0; r < 4; r++)
        #pragma unroll
        for (int p = 0; p < 4; p++) acc[r][p] = 0ull;

    const float* xg = g_xnT + (size_t)m * (ND * NC);
    const float* fT = g_fT + (size_t)n * (ND * NF);

    // staging: thread handles (its group g, k = tid&31, c-half q = (tid>>5)&1)
    const int st_k = tid & 31;
    const int st_q = (tid >> 5) & 1;
    const float* st_src = xg + st_q * 8;             // + k*16 per row
    float* st_base = xs + g * (2 * XBUF);            // + buf*XBUF

    // prime buffer 0
    {
        float4 a = *(const float4*)(st_src + st_k * 16);
        float4 b = *(const float4*)(st_src + st_k * 16 + 4);
        float* d = st_base + st_k * XST + st_q * 16;
        *(float4*)(d)      = make_float4(a.x, a.x, a.y, a.y);
        *(float4*)(d + 4)  = make_float4(a.z, a.z, a.w, a.w);
        *(float4*)(d + 8)  = make_float4(b.x, b.x, b.y, b.y);
        *(float4*)(d + 12) = make_float4(b.z, b.z, b.w, b.w);
    }
    __syncthreads();

    #pragma unroll 1
    for (int chunk = 0; chunk < 16; chunk++) {   // 16 chunks x 32 k
        const float* cur = st_base + (chunk & 1) * XBUF;
        if (chunk < 15) {
            const float* s = st_src + (chunk + 1) * 32 * 16 + st_k * 16;
            float4 a = *(const float4*)(s);
            float4 b = *(const float4*)(s + 4);
            float* d = st_base + ((chunk + 1) & 1) * XBUF
                               + st_k * XST + st_q * 16;
            *(float4*)(d)      = make_float4(a.x, a.x, a.y, a.y);
            *(float4*)(d + 4)  = make_float4(a.z, a.z, a.w, a.w);
            *(float4*)(d + 8)  = make_float4(b.x, b.x, b.y, b.y);
            *(float4*)(d + 12) = make_float4(b.z, b.z, b.w, b.w);
        }

        const float* fk = fT + (size_t)chunk * 32 * NF + fg16 * 8;
        const float* xk = cur + cg * 8;
        #pragma unroll 4
        for (int k = 0; k < 32; k++) {
            // 8 f values = 4 packed pairs, straight from gmem
            ulonglong2 fp0 = *(const ulonglong2*)(fk + (size_t)k * NF);
            ulonglong2 fp1 = *(const ulonglong2*)(fk + (size_t)k * NF + 4);
            // 4 duplicated x pairs from SMEM (broadcast, conflict-free)
            ulonglong2 xa = *(const ulonglong2*)(xk + k * XST);      // c0,c1
            ulonglong2 xb = *(const ulonglong2*)(xk + k * XST + 4);  // c2,c3
            fma2(acc[0][0], xa.x, fp0.x); fma2(acc[0][1], xa.x, fp0.y);
            fma2(acc[0][2], xa.x, fp1.x); fma2(acc[0][3], xa.x, fp1.y);
            fma2(acc[1][0], xa.y, fp0.x); fma2(acc[1][1], xa.y, fp0.y);
            fma2(acc[1][2], xa.y, fp1.x); fma2(acc[1][3], xa.y, fp1.y);
            fma2(acc[2][0], xb.x, fp0.x); fma2(acc[2][1], xb.x, fp0.y);
            fma2(acc[2][2], xb.x, fp1.x); fma2(acc[2][3], xb.x, fp1.y);
            fma2(acc[3][0], xb.y, fp0.x); fma2(acc[3][1], xb.y, fp0.y);
            fma2(acc[3][2], xb.y, fp1.x); fma2(acc[3][3], xb.y, fp1.y);
        }
        __syncthreads();
    }

    const float fnrm = g_fnorm[n * NF + tid];

    // ==== DP + backtrack, once per pair group ====
    for (int gg = 0; gg < 2; gg++) {
        __syncthreads();   // smem free (GEMM done / previous pair done)

        if (g == gg) {
            // spill this group's S to Sbuf[f][c] (stride 17)
            #pragma unroll
            for (int r = 0; r < 4; r++)
                #pragma unroll
                for (int p = 0; p < 4; p++) {
                    unsigned long long v = acc[r][p];
                    float s0 = __uint_as_float((unsigned)(v & 0xffffffffu));
                    float s1 = __uint_as_float((unsigned)(v >> 32));
                    int f = fg16 * 8 + 2 * p, c = cg * 4 + r;
                    Sbuf[f * 17 + c]       = s0;
                    Sbuf[(f + 1) * 17 + c] = s1;
                }
        }
        // init DP row 0 and zero the mask
        Dm[tid + 1] = NEG_INF;
        if (tid == 0) Dm[0] = 0.0f;
        {
            float4 z = make_float4(0.f, 0.f, 0.f, 0.f);
            float4* m4 = (float4*)mask;
            #pragma unroll
            for (int w = 0; w < 4; w++) m4[tid + w * 128] = z;
        }
        __syncthreads();

        // DP rows: D[i,j] = Ccum[j] + cummax_k<=j(A[k] - Ccum[k-1])
        for (int i = 1; i <= NC; i++) {
            const int c = i - 1;
            float s = Sbuf[tid * 17 + c];
            if (tid <= c) s = s / fnrm;   // tri region: normalized similarity

            const float* Pv = Dm + (size_t)(i - 1) * 129;
            float A = fmaxf(Pv[tid], Pv[tid + 1]);   // max(diag, up)

            // inclusive block cumsum of s
            float cs = s;
            #pragma unroll
            for (int o = 1; o < 32; o <<= 1) {
                float t = __shfl_up_sync(0xffffffffu, cs, o);
                if (lane >= o) cs += t;
            }
            if (lane == 31) wrs[wid] = cs;
            __syncthreads();
            float pre = 0.0f;
            if (wid > 0) pre += wrs[0];
            if (wid > 1) pre += wrs[1];
            if (wid > 2) pre += wrs[2];
            float Ccum = pre + cs;
            // Cm1 = Ccum of thread tid-1, reconstructed bit-exactly:
            float csp = __shfl_up_sync(0xffffffffu, cs, 1);
            float Cm1 = (lane == 0) ? pre : (pre + csp);
            float T = A - Cm1;

            // inclusive block cummax of T (exact)
            float mx = T;
            #pragma unroll
            for (int o = 1; o < 32; o <<= 1) {
                float t = __shfl_up_sync(0xffffffffu, mx, o);
                if (lane >= o) mx = fmaxf(mx, t);
            }
            if (lane == 31) wrm[wid] = mx;
            __syncthreads();
            if (wid > 0) mx = fmaxf(mx, wrm[0]);
            if (wid > 1) mx = fmaxf(mx, wrm[1]);
            if (wid > 2) mx = fmaxf(mx, wrm[2]);

            Dm[i * 129 + tid + 1] = Ccum + mx;
            if (tid == 0) Dm[i * 129] = NEG_INF;
            __syncthreads();
        }

        // backtrack (argmax first-max: up > left > diag), serial thread
        if (tid == 0) {
            int i = NC, j = NF;
            #pragma unroll 1
            for (int step = 0; step < NC + NF && (i > 0 && j > 0); step++) {
                mask[(i - 1) * NF + (j - 1)] = 1.0f;
                float up = Dm[(i - 1) * 129 + j];
                float lf = Dm[i * 129 + (j - 1)];
                float dg = Dm[(i - 1) * 129 + (j - 1)];
                int mv;
                if (up >= lf && up >= dg) mv = 0;
                else if (lf >= dg)        mv = 1;
                else                      mv = 2;
                if (mv != 1) i--;
                if (mv != 0) j--;
            }
        }
        __syncthreads();

        // store mask [16][128] coalesced for pair (mbase+gg, n)
        {
            float4* og = (float4*)(out +
                (size_t)((mbase + gg) * NB + n) * (NC * NF));
            const float4* ms4 = (const float4*)mask;
            #pragma unroll
            for (int w = 0; w < 4; w++) og[tid + w * 128] = ms4[tid + w * 128];
        }
    }
}

// ---------------------------------------------------------------------------
extern "C" void kernel_launch(void* const* d_in, const int* in_sizes, int n_in,
                              void* d_out, int out_size)
{
    const float* c_feats = (const float*)d_in[0];
    const float* f_feats = (const float*)d_in[1];
    float* out = (float*)d_out;

    prep_kernel<<<NB * NC + NB * NF, 128>>>(c_feats, f_feats);
    transpose_f_kernel<<<dim3(4, 16, NB), dim3(32, 8)>>>(f_feats);
    dtw_kernel<<<NB * NB / 2, 128>>>(out);
}

// round 13
// speedup vs baseline: 1.6749x; 1.5868x over previous
#include <cuda_runtime.h>
#include <cstdint>

#define NB 128   // batch
#define NC 16    // c rows
#define NF 128   // f cols
#define ND 512   // feature dim
#define NEG_INF __int_as_float(0xff800000)

// Scratch (no cudaMalloc allowed)
__device__ float g_xnT[NB * ND * NC];     // 4 MB  : xn transposed [m][d][c]
__device__ float g_fT [NB * ND * NF];     // 32 MB : f transposed  [n][d][f]
__device__ float g_fnorm[NB * NF];        // 64 KB

// ---------------------------------------------------------------------------
// Kernel 1: normalize c_feats (store d-major transposed) + f row norms
// ---------------------------------------------------------------------------
__global__ void __launch_bounds__(128) prep_kernel(
    const float* __restrict__ c_feats, const float* __restrict__ f_feats)
{
    const int b   = blockIdx.x;
    const int tid = threadIdx.x;
    const bool is_c = (b < NB * NC);
    const float* row = is_c ? (c_feats + (size_t)b * ND)
                            : (f_feats + (size_t)(b - NB * NC) * ND);
    float4 x = ((const float4*)row)[tid];
    float ss = x.x * x.x + x.y * x.y + x.z * x.z + x.w * x.w;
    #pragma unroll
    for (int o = 16; o; o >>= 1) ss += __shfl_xor_sync(0xffffffffu, ss, o);
    __shared__ float wr[4];
    if ((tid & 31) == 0) wr[tid >> 5] = ss;
    __syncthreads();
    float nrm = sqrtf(wr[0] + wr[1] + wr[2] + wr[3]);

    if (is_c) {
        int m = b >> 4, c = b & 15;
        float* dst = g_xnT + (size_t)m * (ND * NC) + c;
        int d0 = tid * 4;
        dst[(size_t)(d0 + 0) * NC] = x.x / nrm;
        dst[(size_t)(d0 + 1) * NC] = x.y / nrm;
        dst[(size_t)(d0 + 2) * NC] = x.z / nrm;
        dst[(size_t)(d0 + 3) * NC] = x.w / nrm;
    } else {
        if (tid == 0) g_fnorm[b - NB * NC] = nrm;
    }
}

// ---------------------------------------------------------------------------
// Kernel 1b: transpose f_feats [n][f][d] -> g_fT [n][d][f]
// ---------------------------------------------------------------------------
__global__ void __launch_bounds__(256) transpose_f_kernel(
    const float* __restrict__ f_feats)
{
    __shared__ float t[32][33];
    const int ft = blockIdx.x, dt = blockIdx.y, n = blockIdx.z;
    const int x = threadIdx.x, y = threadIdx.y;

    const float* src = f_feats + ((size_t)n * NF + ft * 32) * ND + dt * 32;
    #pragma unroll
    for (int r = 0; r < 32; r += 8)
        t[y + r][x] = src[(size_t)(y + r) * ND + x];
    __syncthreads();
    float* dst = g_fT + (size_t)n * (ND * NF) + (size_t)(dt * 32) * NF + ft * 32;
    #pragma unroll
    for (int r = 0; r < 32; r += 8)
        dst[(size_t)(y + r) * NF + x] = t[x][y + r];
}

// ---------------------------------------------------------------------------
// Kernel 2: ONE WARP PER PAIR. 4 pairs per CTA (m=4q..4q+3, same n).
// Lane tile 8c x 8f:  cb = lane>>4 (c rows cb*8..+7), fg = lane&15 (f cols fg*8..+7).
// GEMM straight from gmem (no smem, no CTA syncs):
//   per k per lane: 2 LDG.128 x (packed c-pairs, 1 line/warp)
//                 + 2 LDG.128 f (8 floats) + 8 mov.b64 dup + 32 FFMA2.
// DP + backtrack fully warp-local (shfl scans, per-warp smem buffer).
//
// Per-warp smem B[18][128]:
//   S[c] spilled at row c+2;  Drow_i written at row i (aliases S[i-2],
//   consumed one row earlier).  Path bitmap pb[16][4] per warp.
// ---------------------------------------------------------------------------
#define BROWS 18

__device__ __forceinline__ void fma2(unsigned long long& d,
                                     unsigned long long a,
                                     unsigned long long b) {
    asm("fma.rn.f32x2 %0, %1, %2, %0;" : "+l"(d) : "l"(a), "l"(b));
}
__device__ __forceinline__ unsigned long long dup2(float f) {
    unsigned long long r;
    asm("mov.b64 %0, {%1, %1};" : "=l"(r) : "f"(f));
    return r;
}

__global__ void __launch_bounds__(128, 4) dtw_kernel(float* __restrict__ out)
{
    __shared__ float    B[4][BROWS * NF];   // 36 KB
    __shared__ uint32_t pb[4][64];          // 1 KB path bitmaps

    const int bid = blockIdx.x;
    const int n   = bid >> 5;               // 32 CTAs per n
    const int mb  = (bid & 31) << 2;
    const int tid  = threadIdx.x;
    const int w    = tid >> 5;
    const int lane = tid & 31;
    const int m    = mb + w;
    const int cb   = lane >> 4;             // 0/1 : c rows cb*8..cb*8+7
    const int fg   = lane & 15;             // f cols fg*8..fg*8+7

    // acc[cp][j]: packed pair (S[cb*8+2cp][fg*8+j], S[cb*8+2cp+1][fg*8+j])
    unsigned long long acc[4][8];
    #pragma unroll
    for (int p = 0; p < 4; p++)
        #pragma unroll
        for (int j = 0; j < 8; j++) acc[p][j] = 0ull;

    const float* xp = g_xnT + (size_t)m * (ND * NC) + cb * 8;
    const float* fp = g_fT  + (size_t)n * (ND * NF) + fg * 8;

    #pragma unroll 1
    for (int k0 = 0; k0 < ND; k0 += 4) {
        #pragma unroll
        for (int kk = 0; kk < 4; kk++) {
            const float* xq = xp + kk * NC;
            const float* fq = fp + kk * NF;
            ulonglong2 xa = *(const ulonglong2*)(xq);       // c pairs 0-3
            ulonglong2 xb = *(const ulonglong2*)(xq + 4);   // c pairs 4-7
            float4 fa = *(const float4*)(fq);
            float4 fb = *(const float4*)(fq + 4);
            unsigned long long b0 = dup2(fa.x), b1 = dup2(fa.y),
                               b2 = dup2(fa.z), b3 = dup2(fa.w),
                               b4 = dup2(fb.x), b5 = dup2(fb.y),
                               b6 = dup2(fb.z), b7 = dup2(fb.w);
            fma2(acc[0][0], xa.x, b0); fma2(acc[1][0], xa.y, b0);
            fma2(acc[2][0], xb.x, b0); fma2(acc[3][0], xb.y, b0);
            fma2(acc[0][1], xa.x, b1); fma2(acc[1][1], xa.y, b1);
            fma2(acc[2][1], xb.x, b1); fma2(acc[3][1], xb.y, b1);
            fma2(acc[0][2], xa.x, b2); fma2(acc[1][2], xa.y, b2);
            fma2(acc[2][2], xb.x, b2); fma2(acc[3][2], xb.y, b2);
            fma2(acc[0][3], xa.x, b3); fma2(acc[1][3], xa.y, b3);
            fma2(acc[2][3], xb.x, b3); fma2(acc[3][3], xb.y, b3);
            fma2(acc[0][4], xa.x, b4); fma2(acc[1][4], xa.y, b4);
            fma2(acc[2][4], xb.x, b4); fma2(acc[3][4], xb.y, b4);
            fma2(acc[0][5], xa.x, b5); fma2(acc[1][5], xa.y, b5);
            fma2(acc[2][5], xb.x, b5); fma2(acc[3][5], xb.y, b5);
            fma2(acc[0][6], xa.x, b6); fma2(acc[1][6], xa.y, b6);
            fma2(acc[2][6], xb.x, b6); fma2(acc[3][6], xb.y, b6);
            fma2(acc[0][7], xa.x, b7); fma2(acc[1][7], xa.y, b7);
            fma2(acc[2][7], xb.x, b7); fma2(acc[3][7], xb.y, b7);
        }
        xp += 4 * NC;
        fp += 4 * NF;
    }

    // ---- spill S into per-warp buffer: S[c] -> B[w][(c+2)*NF + f] ----
    float* Bw = B[w];
    #pragma unroll
    for (int p = 0; p < 4; p++)
        #pragma unroll
        for (int j = 0; j < 8; j++) {
            unsigned long long v = acc[p][j];
            int c = cb * 8 + 2 * p, f = fg * 8 + j;
            Bw[(c + 2) * NF + f] = __uint_as_float((unsigned)(v & 0xffffffffu));
            Bw[(c + 3) * NF + f] = __uint_as_float((unsigned)(v >> 32));
        }
    uint32_t* pbw = pb[w];
    pbw[lane] = 0u; pbw[lane + 32] = 0u;
    __syncwarp();

    // ---- warp-local DP: lane owns f indices j4..j4+3 ----
    const int j4 = lane * 4;
    const float4 fn4 = *(const float4*)(g_fnorm + n * NF + j4);

    #pragma unroll 1
    for (int i = 1; i <= NC; i++) {
        const int c = i - 1;
        float4 s4 = *(const float4*)(Bw + (c + 2) * NF + j4);
        float s0 = s4.x, s1 = s4.y, s2 = s4.z, s3 = s4.w;
        if (j4 + 0 <= c) s0 /= fn4.x;       // tri region: normalized sim
        if (j4 + 1 <= c) s1 /= fn4.y;
        if (j4 + 2 <= c) s2 /= fn4.z;
        if (j4 + 3 <= c) s3 /= fn4.w;

        float A0, A1, A2, A3;
        if (i == 1) {
            A0 = (lane == 0) ? 0.0f : NEG_INF;
            A1 = NEG_INF; A2 = NEG_INF; A3 = NEG_INF;
        } else {
            float4 dp = *(const float4*)(Bw + (i - 1) * NF + j4);
            float dm1 = (lane == 0) ? NEG_INF : Bw[(i - 1) * NF + j4 - 1];
            A0 = fmaxf(dm1,  dp.x);
            A1 = fmaxf(dp.x, dp.y);
            A2 = fmaxf(dp.y, dp.z);
            A3 = fmaxf(dp.z, dp.w);
        }

        // cumsum (local sequential + warp inclusive scan of lane totals)
        float l0 = s0, l1 = l0 + s1, l2 = l1 + s2, l3 = l2 + s3;
        float run = l3;
        #pragma unroll
        for (int o = 1; o < 32; o <<= 1) {
            float t = __shfl_up_sync(0xffffffffu, run, o);
            if (lane >= o) run += t;
        }
        float excl = __shfl_up_sync(0xffffffffu, run - l3 + l3, 1); // = run of prev
        excl = __shfl_up_sync(0xffffffffu, run, 1);
        if (lane == 0) excl = 0.0f;
        // Ccum[t] = excl + l_t ; Cm1[t] = Ccum[t-1] (bit-consistent)
        float C0 = excl + l0, C1 = excl + l1, C2 = excl + l2, C3 = excl + l3;
        float cm1_0 = __shfl_up_sync(0xffffffffu, C3, 1);
        if (lane == 0) cm1_0 = 0.0f;

        float T0 = A0 - cm1_0;
        float T1 = A1 - C0;
        float T2 = A2 - C1;
        float T3 = A3 - C2;

        // cummax (exact: order-independent)
        float g0 = T0, g1 = fmaxf(g0, T1), g2 = fmaxf(g1, T2), g3 = fmaxf(g2, T3);
        float mrun = g3;
        #pragma unroll
        for (int o = 1; o < 32; o <<= 1) {
            float t = __shfl_up_sync(0xffffffffu, mrun, o);
            if (lane >= o) mrun = fmaxf(mrun, t);
        }
        float mex = __shfl_up_sync(0xffffffffu, mrun, 1);
        if (lane == 0) mex = NEG_INF;

        float4 D;
        D.x = C0 + fmaxf(mex, g0);
        D.y = C1 + fmaxf(mex, g1);
        D.z = C2 + fmaxf(mex, g2);
        D.w = C3 + fmaxf(mex, g3);
        *(float4*)(Bw + i * NF + j4) = D;
        __syncwarp();
    }

    // ---- backtrack (lane 0): priority up > left > diag (first-max) ----
    if (lane == 0) {
        int i = NC, j = NF;
        #pragma unroll 1
        while (i > 0 && j > 0) {
            pbw[(i - 1) * 4 + ((j - 1) >> 5)] |= 1u << ((j - 1) & 31);
            float up = (i - 1 == 0) ? NEG_INF : Bw[(i - 1) * NF + j - 1];
            float lf = (j - 1 == 0) ? NEG_INF : Bw[i * NF + j - 2];
            float dg;
            if (i - 1 == 0)      dg = (j - 1 == 0) ? 0.0f : NEG_INF;
            else if (j - 1 == 0) dg = NEG_INF;
            else                 dg = Bw[(i - 1) * NF + j - 2];
            int mv = (up >= lf && up >= dg) ? 0 : ((lf >= dg) ? 1 : 2);
            if (mv != 1) i--;
            if (mv != 0) j--;
        }
    }
    __syncwarp();

    // ---- expand bitmap -> mask, single coalesced STG.128 pass ----
    float* op = out + ((size_t)m * NB + n) * (NC * NF);
    #pragma unroll
    for (int q = 0; q < NC; q++) {
        uint32_t bits = pbw[q * 4 + (lane >> 3)] >> ((lane & 7) * 4);
        float4 v;
        v.x = (bits & 1u) ? 1.0f : 0.0f;
        v.y = (bits & 2u) ? 1.0f : 0.0f;
        v.z = (bits & 4u) ? 1.0f : 0.0f;
        v.w = (bits & 8u) ? 1.0f : 0.0f;
        *(float4*)(op + q * NF + j4) = v;
    }
}

// ---------------------------------------------------------------------------
extern "C" void kernel_launch(void* const* d_in, const int* in_sizes, int n_in,
                              void* d_out, int out_size)
{
    const float* c_feats = (const float*)d_in[0];
    const float* f_feats = (const float*)d_in[1];
    float* out = (float*)d_out;

    prep_kernel<<<NB * NC + NB * NF, 128>>>(c_feats, f_feats);
    transpose_f_kernel<<<dim3(4, 16, NB), dim3(32, 8)>>>(f_feats);
    dtw_kernel<<<NB * NB / 4, 128>>>(out);
}

// round 16
// speedup vs baseline: 1.8141x; 1.0831x over previous
#include <cuda_runtime.h>
#include <cstdint>

#define NB 128   // batch
#define NC 16    // c rows
#define NF 128   // f cols
#define ND 512   // feature dim
#define NEG_INF __int_as_float(0xff800000)

// Scratch (no cudaMalloc allowed)
__device__ float g_xnT[NB * ND * NC];        // 4 MB  : xn transposed [m][d][c]
__device__ float g_fT [NB * ND * NF];        // 32 MB : f transposed  [n][d][f]
__device__ float g_fnorm[NB * NF];           // 64 KB
__device__ float g_S[(size_t)NB * NB * NC * NF];   // 134 MB : raw S per pair

// ---------------------------------------------------------------------------
// Kernel 1: normalize c_feats (store d-major transposed) + f row norms
// ---------------------------------------------------------------------------
__global__ void __launch_bounds__(128) prep_kernel(
    const float* __restrict__ c_feats, const float* __restrict__ f_feats)
{
    const int b   = blockIdx.x;
    const int tid = threadIdx.x;
    const bool is_c = (b < NB * NC);
    const float* row = is_c ? (c_feats + (size_t)b * ND)
                            : (f_feats + (size_t)(b - NB * NC) * ND);
    float4 x = ((const float4*)row)[tid];
    float ss = x.x * x.x + x.y * x.y + x.z * x.z + x.w * x.w;
    #pragma unroll
    for (int o = 16; o; o >>= 1) ss += __shfl_xor_sync(0xffffffffu, ss, o);
    __shared__ float wr[4];
    if ((tid & 31) == 0) wr[tid >> 5] = ss;
    __syncthreads();
    float nrm = sqrtf(wr[0] + wr[1] + wr[2] + wr[3]);

    if (is_c) {
        int m = b >> 4, c = b & 15;
        float* dst = g_xnT + (size_t)m * (ND * NC) + c;
        int d0 = tid * 4;
        dst[(size_t)(d0 + 0) * NC] = x.x / nrm;
        dst[(size_t)(d0 + 1) * NC] = x.y / nrm;
        dst[(size_t)(d0 + 2) * NC] = x.z / nrm;
        dst[(size_t)(d0 + 3) * NC] = x.w / nrm;
    } else {
        if (tid == 0) g_fnorm[b - NB * NC] = nrm;
    }
}

// ---------------------------------------------------------------------------
// Kernel 1b: transpose f_feats [n][f][d] -> g_fT [n][d][f]
// ---------------------------------------------------------------------------
__global__ void __launch_bounds__(256) transpose_f_kernel(
    const float* __restrict__ f_feats)
{
    __shared__ float t[32][33];
    const int ft = blockIdx.x, dt = blockIdx.y, n = blockIdx.z;
    const int x = threadIdx.x, y = threadIdx.y;

    const float* src = f_feats + ((size_t)n * NF + ft * 32) * ND + dt * 32;
    #pragma unroll
    for (int r = 0; r < 32; r += 8)
        t[y + r][x] = src[(size_t)(y + r) * ND + x];
    __syncthreads();
    float* dst = g_fT + (size_t)n * (ND * NF) + (size_t)(dt * 32) * NF + ft * 32;
    #pragma unroll
    for (int r = 0; r < 32; r += 8)
        dst[(size_t)(y + r) * NF + x] = t[x][y + r];
}

// ---------------------------------------------------------------------------
// Kernel B: PURE GEMM. One warp per pair, 4 pairs/CTA (same n), no smem.
// Lane tile 8c x 8f, identical FMA order to R12 (S bit-exact).
// S spilled raw (unnormalized) to g_S[pair][c][f].
// ---------------------------------------------------------------------------
__device__ __forceinline__ void fma2(unsigned long long& d,
                                     unsigned long long a,
                                     unsigned long long b) {
    asm("fma.rn.f32x2 %0, %1, %2, %0;" : "+l"(d) : "l"(a), "l"(b));
}
__device__ __forceinline__ unsigned long long dup2(float f) {
    unsigned long long r;
    asm("mov.b64 %0, {%1, %1};" : "=l"(r) : "f"(f));
    return r;
}
__device__ __forceinline__ float lo32(unsigned long long v) {
    return __uint_as_float((unsigned)(v & 0xffffffffu));
}
__device__ __forceinline__ float hi32(unsigned long long v) {
    return __uint_as_float((unsigned)(v >> 32));
}

__global__ void __launch_bounds__(128, 4) gemm_kernel()
{
    const int bid = blockIdx.x;
    const int n   = bid >> 5;               // 32 CTAs per n
    const int mb  = (bid & 31) << 2;
    const int tid  = threadIdx.x;
    const int w    = tid >> 5;
    const int lane = tid & 31;
    const int m    = mb + w;
    const int cb   = lane >> 4;             // c rows cb*8..cb*8+7
    const int fg   = lane & 15;             // f cols fg*8..fg*8+7

    unsigned long long acc[4][8];
    #pragma unroll
    for (int p = 0; p < 4; p++)
        #pragma unroll
        for (int j = 0; j < 8; j++) acc[p][j] = 0ull;

    const float* xp = g_xnT + (size_t)m * (ND * NC) + cb * 8;
    const float* fp = g_fT  + (size_t)n * (ND * NF) + fg * 8;

    #pragma unroll 1
    for (int k0 = 0; k0 < ND; k0 += 4) {
        #pragma unroll
        for (int kk = 0; kk < 4; kk++) {
            const float* xq = xp + kk * NC;
            const float* fq = fp + kk * NF;
            ulonglong2 xa = *(const ulonglong2*)(xq);
            ulonglong2 xb = *(const ulonglong2*)(xq + 4);
            float4 fa = *(const float4*)(fq);
            float4 fb = *(const float4*)(fq + 4);
            unsigned long long b0 = dup2(fa.x), b1 = dup2(fa.y),
                               b2 = dup2(fa.z), b3 = dup2(fa.w),
                               b4 = dup2(fb.x), b5 = dup2(fb.y),
                               b6 = dup2(fb.z), b7 = dup2(fb.w);
            fma2(acc[0][0], xa.x, b0); fma2(acc[1][0], xa.y, b0);
            fma2(acc[2][0], xb.x, b0); fma2(acc[3][0], xb.y, b0);
            fma2(acc[0][1], xa.x, b1); fma2(acc[1][1], xa.y, b1);
            fma2(acc[2][1], xb.x, b1); fma2(acc[3][1], xb.y, b1);
            fma2(acc[0][2], xa.x, b2); fma2(acc[1][2], xa.y, b2);
            fma2(acc[2][2], xb.x, b2); fma2(acc[3][2], xb.y, b2);
            fma2(acc[0][3], xa.x, b3); fma2(acc[1][3], xa.y, b3);
            fma2(acc[2][3], xb.x, b3); fma2(acc[3][3], xb.y, b3);
            fma2(acc[0][4], xa.x, b4); fma2(acc[1][4], xa.y, b4);
            fma2(acc[2][4], xb.x, b4); fma2(acc[3][4], xb.y, b4);
            fma2(acc[0][5], xa.x, b5); fma2(acc[1][5], xa.y, b5);
            fma2(acc[2][5], xb.x, b5); fma2(acc[3][5], xb.y, b5);
            fma2(acc[0][6], xa.x, b6); fma2(acc[1][6], xa.y, b6);
            fma2(acc[2][6], xb.x, b6); fma2(acc[3][6], xb.y, b6);
            fma2(acc[0][7], xa.x, b7); fma2(acc[1][7], xa.y, b7);
            fma2(acc[2][7], xb.x, b7); fma2(acc[3][7], xb.y, b7);
        }
        xp += 4 * NC;
        fp += 4 * NF;
    }

    // spill raw S: rows c = cb*8+2p (lows) and +1 (highs), cols fg*8..+7
    float* Sp = g_S + (size_t)(m * NB + n) * (NC * NF);
    #pragma unroll
    for (int p = 0; p < 4; p++) {
        int c0 = cb * 8 + 2 * p;
        float* r0 = Sp + (size_t)c0 * NF + fg * 8;
        float* r1 = r0 + NF;
        *(float4*)(r0)     = make_float4(lo32(acc[p][0]), lo32(acc[p][1]),
                                         lo32(acc[p][2]), lo32(acc[p][3]));
        *(float4*)(r0 + 4) = make_float4(lo32(acc[p][4]), lo32(acc[p][5]),
                                         lo32(acc[p][6]), lo32(acc[p][7]));
        *(float4*)(r1)     = make_float4(hi32(acc[p][0]), hi32(acc[p][1]),
                                         hi32(acc[p][2]), hi32(acc[p][3]));
        *(float4*)(r1 + 4) = make_float4(hi32(acc[p][4]), hi32(acc[p][5]),
                                         hi32(acc[p][6]), hi32(acc[p][7]));
    }
}

// ---------------------------------------------------------------------------
// Kernel C: DP + backtrack. One warp per pair, 8 warps/CTA.
// D rows in registers (shfl for j-1 boundary); 2-bit move table in smem
// (512 B/warp) written during the forward pass; uniform-backtrack with a
// per-lane 64-bit path bitmap; mask stored straight from the bitmap.
// ---------------------------------------------------------------------------
__global__ void __launch_bounds__(256) dp_kernel(float* __restrict__ out)
{
    __shared__ uint8_t mvs[8][NC * 32];     // [warp][row*32 + colgroup]

    const int tid  = threadIdx.x;
    const int w    = tid >> 5;
    const int lane = tid & 31;
    const int p    = blockIdx.x * 8 + w;    // pair = m*NB + n
    const int n    = p & 127;
    const int j4   = lane * 4;              // f cols j4..j4+3 (0-based)

    const float4* Sp = (const float4*)(g_S + (size_t)p * (NC * NF));
    const float4  fn4 = *(const float4*)(g_fnorm + n * NF + j4);
    uint8_t* mvw = mvs[w];

    float4 prev = make_float4(NEG_INF, NEG_INF, NEG_INF, NEG_INF);
    float4 qa = Sp[lane];            // row 0
    float4 qb = Sp[32 + lane];       // row 1

    #pragma unroll
    for (int i = 1; i <= NC; i++) {
        const int c = i - 1;
        float4 s4 = qa;
        qa = qb;
        if (i <= NC - 2) qb = Sp[(i + 1) * 32 + lane];

        float s0 = s4.x, s1 = s4.y, s2 = s4.z, s3 = s4.w;
        if (j4 + 0 <= c) s0 /= fn4.x;       // tri region: normalized sim
        if (j4 + 1 <= c) s1 /= fn4.y;
        if (j4 + 2 <= c) s2 /= fn4.z;
        if (j4 + 3 <= c) s3 /= fn4.w;

        // boundary Dm[i-1][j4-1]
        float pm1 = __shfl_up_sync(0xffffffffu, prev.w, 1);
        if (lane == 0) pm1 = (i == 1) ? 0.0f : NEG_INF;
        float A0 = fmaxf(pm1,    prev.x);
        float A1 = fmaxf(prev.x, prev.y);
        float A2 = fmaxf(prev.y, prev.z);
        float A3 = fmaxf(prev.z, prev.w);

        // cumsum (local sequential + warp scan of lane totals) — R12-exact
        float l0 = s0, l1 = l0 + s1, l2 = l1 + s2, l3 = l2 + s3;
        float run = l3;
        #pragma unroll
        for (int o = 1; o < 32; o <<= 1) {
            float t = __shfl_up_sync(0xffffffffu, run, o);
            if (lane >= o) run += t;
        }
        float excl = __shfl_up_sync(0xffffffffu, run, 1);
        if (lane == 0) excl = 0.0f;
        float C0 = excl + l0, C1 = excl + l1, C2 = excl + l2, C3 = excl + l3;
        float cm1_0 = __shfl_up_sync(0xffffffffu, C3, 1);
        if (lane == 0) cm1_0 = 0.0f;

        float T0 = A0 - cm1_0;
        float T1 = A1 - C0;
        float T2 = A2 - C1;
        float T3 = A3 - C2;

        // cummax (exact)
        float g0 = T0, g1 = fmaxf(g0, T1), g2 = fmaxf(g1, T2), g3 = fmaxf(g2, T3);
        float mrun = g3;
        #pragma unroll
        for (int o = 1; o < 32; o <<= 1) {
            float t = __shfl_up_sync(0xffffffffu, mrun, o);
            if (lane >= o) mrun = fmaxf(mrun, t);
        }
        float mex = __shfl_up_sync(0xffffffffu, mrun, 1);
        if (lane == 0) mex = NEG_INF;

        float4 cur;
        cur.x = C0 + fmaxf(mex, g0);
        cur.y = C1 + fmaxf(mex, g1);
        cur.z = C2 + fmaxf(mex, g2);
        cur.w = C3 + fmaxf(mex, g3);

        // move decisions for row i (priority up > left > diag, first-max)
        float cm1 = __shfl_up_sync(0xffffffffu, cur.w, 1);
        if (lane == 0) cm1 = NEG_INF;       // Dm[i][0]
        float up0 = prev.x, up1 = prev.y, up2 = prev.z, up3 = prev.w;
        float dg0 = pm1,    dg1 = prev.x, dg2 = prev.y, dg3 = prev.z;
        float lf0 = cm1,    lf1 = cur.x,  lf2 = cur.y,  lf3 = cur.z;
        int mv0 = (up0 >= lf0 && up0 >= dg0) ? 0 : ((lf0 >= dg0) ? 1 : 2);
        int mv1 = (up1 >= lf1 && up1 >= dg1) ? 0 : ((lf1 >= dg1) ? 1 : 2);
        int mv2 = (up2 >= lf2 && up2 >= dg2) ? 0 : ((lf2 >= dg2) ? 1 : 2);
        int mv3 = (up3 >= lf3 && up3 >= dg3) ? 0 : ((lf3 >= dg3) ? 1 : 2);
        mvw[c * 32 + lane] =
            (uint8_t)(mv0 | (mv1 << 2) | (mv2 << 4) | (mv3 << 6));

        prev = cur;
    }
    __syncwarp();

    // ---- backtrack: uniform loop, all lanes converged ----
    uint64_t path = 0ull;
    {
        int i = NC, j = NF;
        #pragma unroll 1
        while (i > 0 && j > 0) {
            int row = i - 1, col = j - 1;
            if ((col >> 2) == lane)
                path |= 1ull << (row * 4 + (col & 3));
            uint32_t byte = mvw[row * 32 + (col >> 2)];
            int mv = (byte >> ((col & 3) * 2)) & 3;
            i -= (mv != 1);
            j -= (mv != 0);
        }
    }

    // ---- store mask straight from bitmap (every cell written) ----
    float* op = out + (size_t)p * (NC * NF);
    #pragma unroll
    for (int c = 0; c < NC; c++) {
        uint32_t bits = (uint32_t)(path >> (c * 4)) & 0xFu;
        float4 v;
        v.x = (bits & 1u) ? 1.0f : 0.0f;
        v.y = (bits & 2u) ? 1.0f : 0.0f;
        v.z = (bits & 4u) ? 1.0f : 0.0f;
        v.w = (bits & 8u) ? 1.0f : 0.0f;
        *(float4*)(op + c * NF + j4) = v;
    }
}

// ---------------------------------------------------------------------------
extern "C" void kernel_launch(void* const* d_in, const int* in_sizes, int n_in,
                              void* d_out, int out_size)
{
    const float* c_feats = (const float*)d_in[0];
    const float* f_feats = (const float*)d_in[1];
    float* out = (float*)d_out;

    prep_kernel<<<NB * NC + NB * NF, 128>>>(c_feats, f_feats);
    transpose_f_kernel<<<dim3(4, 16, NB), dim3(32, 8)>>>(f_feats);
    gemm_kernel<<<NB * NB / 4, 128>>>();
    dp_kernel<<<NB * NB / 8, 256>>>(out);
}